// round 4
// baseline (speedup 1.0000x reference)
#include <cuda_runtime.h>
#include <math.h>

#define Bsz 4
#define SEQ 2048
#define DIM 1024
#define NH  16
#define DKH 64
#define MTOT (Bsz*SEQ)   // 8192

// ---- scratch (static device globals: allocation-free) ----
__device__ float g_Q[(size_t)Bsz*NH*SEQ*DKH];   // [B,H,S,DK]
__device__ float g_K[(size_t)Bsz*NH*SEQ*DKH];
__device__ float g_V[(size_t)Bsz*NH*SEQ*DKH];
__device__ float g_A[(size_t)MTOT*DIM];         // attention out, [B,S,D]

// ============================================================
// GEMM: C[M,N] = A[M,K] @ W[N,K]^T + bias   (M=8192, N=K=1024)
// headLayout=1: scatter C into [B,H,S,DK]
// ============================================================
#define BM 128
#define BN 128
#define BK 16

__global__ __launch_bounds__(256, 2)
void gemm_nt_kernel(const float* __restrict__ A, const float* __restrict__ W,
                    const float* __restrict__ bias, float* __restrict__ C,
                    int headLayout)
{
    __shared__ float As[BK][BM + 4];
    __shared__ float Bs[BK][BN + 4];
    const int tid = threadIdx.x;
    const int tx = tid & 15, ty = tid >> 4;
    const int m0 = blockIdx.y * BM, n0 = blockIdx.x * BN;
    const int K = DIM, N = DIM;

    float acc[8][8];
    #pragma unroll
    for (int i = 0; i < 8; i++)
        #pragma unroll
        for (int j = 0; j < 8; j++) acc[i][j] = 0.f;

    for (int k0 = 0; k0 < K; k0 += BK) {
        #pragma unroll
        for (int u = 0; u < 2; ++u) {
            int r  = (tid >> 2) + u * 64;
            int c4 = (tid & 3) << 2;
            float4 av = *(const float4*)(A + (size_t)(m0 + r) * K + k0 + c4);
            As[c4+0][r] = av.x; As[c4+1][r] = av.y;
            As[c4+2][r] = av.z; As[c4+3][r] = av.w;
            float4 bv = *(const float4*)(W + (size_t)(n0 + r) * K + k0 + c4);
            Bs[c4+0][r] = bv.x; Bs[c4+1][r] = bv.y;
            Bs[c4+2][r] = bv.z; Bs[c4+3][r] = bv.w;
        }
        __syncthreads();
        #pragma unroll
        for (int kk = 0; kk < BK; ++kk) {
            float a[8], b[8];
            *(float4*)&a[0] = *(const float4*)&As[kk][ty * 8];
            *(float4*)&a[4] = *(const float4*)&As[kk][ty * 8 + 4];
            *(float4*)&b[0] = *(const float4*)&Bs[kk][tx * 8];
            *(float4*)&b[4] = *(const float4*)&Bs[kk][tx * 8 + 4];
            #pragma unroll
            for (int i = 0; i < 8; i++)
                #pragma unroll
                for (int j = 0; j < 8; j++)
                    acc[i][j] = fmaf(a[i], b[j], acc[i][j]);
        }
        __syncthreads();
    }

    float bb[8];
    *(float4*)&bb[0] = *(const float4*)(bias + n0 + tx * 8);
    *(float4*)&bb[4] = *(const float4*)(bias + n0 + tx * 8 + 4);

    if (!headLayout) {
        #pragma unroll
        for (int i = 0; i < 8; i++) {
            int m = m0 + ty * 8 + i;
            float* cp = C + (size_t)m * N + n0 + tx * 8;
            float4 v0 = make_float4(acc[i][0]+bb[0], acc[i][1]+bb[1], acc[i][2]+bb[2], acc[i][3]+bb[3]);
            float4 v1 = make_float4(acc[i][4]+bb[4], acc[i][5]+bb[5], acc[i][6]+bb[6], acc[i][7]+bb[7]);
            *(float4*)cp = v0;
            *(float4*)(cp + 4) = v1;
        }
    } else {
        int n = n0 + tx * 8;
        int h = n >> 6, d0 = n & 63;   // 8-wide span never crosses a head boundary
        #pragma unroll
        for (int i = 0; i < 8; i++) {
            int m = m0 + ty * 8 + i;
            int bb_ = m >> 11, ss = m & 2047;
            float* cp = C + ((((size_t)bb_ * NH + h) * SEQ + ss) * DKH) + d0;
            float4 v0 = make_float4(acc[i][0]+bb[0], acc[i][1]+bb[1], acc[i][2]+bb[2], acc[i][3]+bb[3]);
            float4 v1 = make_float4(acc[i][4]+bb[4], acc[i][5]+bb[5], acc[i][6]+bb[6], acc[i][7]+bb[7]);
            *(float4*)cp = v0;
            *(float4*)(cp + 4) = v1;
        }
    }
}

// ============================================================
// Flash attention: one block per (b, h, 64-row q-tile)
// 256 threads as 16x16; each thread owns a 4x4 microtile.
// smem: Q^T[64][68], {K^T|P}[64][68], V[64][68]
// ============================================================
#define PAD 68
#define SM_Q 0
#define SM_KP (64 * PAD)
#define SM_V  (2 * 64 * PAD)

__global__ __launch_bounds__(256)
void attn_kernel(const int* __restrict__ mask)
{
    extern __shared__ float sm[];
    float* Qts = sm + SM_Q;
    float* KPs = sm + SM_KP;
    float* Vs  = sm + SM_V;

    const int tid = threadIdx.x;
    const int tx = tid & 15, ty = tid >> 4;
    const int q0 = blockIdx.x * 64;
    const int h = blockIdx.y, b = blockIdx.z;

    const float* Qp = g_Q + (((size_t)b * NH + h) * SEQ + q0) * DKH;
    const float* Kb = g_K + (((size_t)b * NH + h) * SEQ) * DKH;
    const float* Vb = g_V + (((size_t)b * NH + h) * SEQ) * DKH;

    // load Q tile transposed: Qts[d][r]
    #pragma unroll
    for (int u = 0; u < 4; ++u) {
        int f = tid + u * 256;
        int r = f >> 4, d4 = (f & 15) << 2;
        float4 v = *(const float4*)(Qp + r * DKH + d4);
        Qts[(d4+0)*PAD + r] = v.x; Qts[(d4+1)*PAD + r] = v.y;
        Qts[(d4+2)*PAD + r] = v.z; Qts[(d4+3)*PAD + r] = v.w;
    }

    float Ot[4][4];
    #pragma unroll
    for (int i = 0; i < 4; i++)
        #pragma unroll
        for (int j = 0; j < 4; j++) Ot[i][j] = 0.f;
    float mi[4] = {-1e30f, -1e30f, -1e30f, -1e30f};
    float li[4] = {0.f, 0.f, 0.f, 0.f};

    const int* mrow = mask + ((size_t)b * SEQ + q0 + ty * 4) * SEQ;

    for (int k0 = 0; k0 < SEQ; k0 += 64) {
        // load K tile transposed + V tile natural
        #pragma unroll
        for (int u = 0; u < 4; ++u) {
            int f = tid + u * 256;
            int r = f >> 4, d4 = (f & 15) << 2;
            float4 kv = *(const float4*)(Kb + (size_t)(k0 + r) * DKH + d4);
            KPs[(d4+0)*PAD + r] = kv.x; KPs[(d4+1)*PAD + r] = kv.y;
            KPs[(d4+2)*PAD + r] = kv.z; KPs[(d4+3)*PAD + r] = kv.w;
            float4 vv = *(const float4*)(Vb + (size_t)(k0 + r) * DKH + d4);
            *(float4*)&Vs[r * PAD + d4] = vv;
        }
        __syncthreads();

        // S = Q K^T
        float s[4][4];
        #pragma unroll
        for (int i = 0; i < 4; i++)
            #pragma unroll
            for (int j = 0; j < 4; j++) s[i][j] = 0.f;
        #pragma unroll 16
        for (int d = 0; d < 64; ++d) {
            float4 qa = *(const float4*)&Qts[d * PAD + ty * 4];
            float4 kb = *(const float4*)&KPs[d * PAD + tx * 4];
            float qr[4] = {qa.x, qa.y, qa.z, qa.w};
            float kr[4] = {kb.x, kb.y, kb.z, kb.w};
            #pragma unroll
            for (int i = 0; i < 4; i++)
                #pragma unroll
                for (int j = 0; j < 4; j++)
                    s[i][j] = fmaf(qr[i], kr[j], s[i][j]);
        }

        // mask + online softmax (row group = 16 lanes sharing ty)
        #pragma unroll
        for (int i = 0; i < 4; i++) {
            const int4 mk = *(const int4*)(mrow + (size_t)i * SEQ + k0 + tx * 4);
            s[i][0] = mk.x ? s[i][0] * 0.125f : -1e9f;
            s[i][1] = mk.y ? s[i][1] * 0.125f : -1e9f;
            s[i][2] = mk.z ? s[i][2] * 0.125f : -1e9f;
            s[i][3] = mk.w ? s[i][3] * 0.125f : -1e9f;

            float mx = fmaxf(fmaxf(s[i][0], s[i][1]), fmaxf(s[i][2], s[i][3]));
            #pragma unroll
            for (int o = 8; o > 0; o >>= 1)
                mx = fmaxf(mx, __shfl_xor_sync(0xffffffffu, mx, o));
            float mn = fmaxf(mi[i], mx);
            float corr = __expf(mi[i] - mn);
            mi[i] = mn;
            float rs = 0.f;
            #pragma unroll
            for (int j = 0; j < 4; j++) {
                s[i][j] = __expf(s[i][j] - mn);
                rs += s[i][j];
            }
            #pragma unroll
            for (int o = 8; o > 0; o >>= 1)
                rs += __shfl_xor_sync(0xffffffffu, rs, o);
            li[i] = li[i] * corr + rs;
            #pragma unroll
            for (int j = 0; j < 4; j++) Ot[i][j] *= corr;
        }
        __syncthreads();   // everyone done reading K^T from KPs

        // stage P into KPs
        #pragma unroll
        for (int i = 0; i < 4; i++)
            *(float4*)&KPs[(ty * 4 + i) * PAD + tx * 4] =
                make_float4(s[i][0], s[i][1], s[i][2], s[i][3]);
        __syncthreads();

        // O += P V
        #pragma unroll 8
        for (int c = 0; c < 64; ++c) {
            float4 vv = *(const float4*)&Vs[c * PAD + tx * 4];
            float p0 = KPs[(ty * 4 + 0) * PAD + c];
            float p1 = KPs[(ty * 4 + 1) * PAD + c];
            float p2 = KPs[(ty * 4 + 2) * PAD + c];
            float p3 = KPs[(ty * 4 + 3) * PAD + c];
            Ot[0][0] = fmaf(p0, vv.x, Ot[0][0]); Ot[0][1] = fmaf(p0, vv.y, Ot[0][1]);
            Ot[0][2] = fmaf(p0, vv.z, Ot[0][2]); Ot[0][3] = fmaf(p0, vv.w, Ot[0][3]);
            Ot[1][0] = fmaf(p1, vv.x, Ot[1][0]); Ot[1][1] = fmaf(p1, vv.y, Ot[1][1]);
            Ot[1][2] = fmaf(p1, vv.z, Ot[1][2]); Ot[1][3] = fmaf(p1, vv.w, Ot[1][3]);
            Ot[2][0] = fmaf(p2, vv.x, Ot[2][0]); Ot[2][1] = fmaf(p2, vv.y, Ot[2][1]);
            Ot[2][2] = fmaf(p2, vv.z, Ot[2][2]); Ot[2][3] = fmaf(p2, vv.w, Ot[2][3]);
            Ot[3][0] = fmaf(p3, vv.x, Ot[3][0]); Ot[3][1] = fmaf(p3, vv.y, Ot[3][1]);
            Ot[3][2] = fmaf(p3, vv.z, Ot[3][2]); Ot[3][3] = fmaf(p3, vv.w, Ot[3][3]);
        }
        __syncthreads();   // before next tile overwrites KPs/Vs
    }

    // normalize + write [B,S,D] with head column offset
    #pragma unroll
    for (int i = 0; i < 4; i++) {
        float inv = 1.f / li[i];
        float* op = g_A + ((size_t)b * SEQ + q0 + ty * 4 + i) * DIM + h * DKH + tx * 4;
        *(float4*)op = make_float4(Ot[i][0]*inv, Ot[i][1]*inv, Ot[i][2]*inv, Ot[i][3]*inv);
    }
}

// ============================================================
extern "C" void kernel_launch(void* const* d_in, const int* in_sizes, int n_in,
                              void* d_out, int out_size)
{
    const float* q    = (const float*)d_in[0];
    const float* k    = (const float*)d_in[1];
    const float* v    = (const float*)d_in[2];
    const int*   mask = (const int*)  d_in[3];
    const float* Wq   = (const float*)d_in[4];
    const float* bq   = (const float*)d_in[5];
    const float* Wk   = (const float*)d_in[6];
    const float* bk   = (const float*)d_in[7];
    const float* Wv   = (const float*)d_in[8];
    const float* bv   = (const float*)d_in[9];
    const float* Wo   = (const float*)d_in[10];
    const float* bo   = (const float*)d_in[11];
    float* out = (float*)d_out;

    float *pQ, *pK, *pV, *pA;
    cudaGetSymbolAddress((void**)&pQ, g_Q);
    cudaGetSymbolAddress((void**)&pK, g_K);
    cudaGetSymbolAddress((void**)&pV, g_V);
    cudaGetSymbolAddress((void**)&pA, g_A);

    dim3 gg(DIM / BN, MTOT / BM);   // (8, 64)
    gemm_nt_kernel<<<gg, 256>>>(q, Wq, bq, pQ, 1);
    gemm_nt_kernel<<<gg, 256>>>(k, Wk, bk, pK, 1);
    gemm_nt_kernel<<<gg, 256>>>(v, Wv, bv, pV, 1);

    size_t smem = 3 * 64 * PAD * sizeof(float);   // 52224 B
    cudaFuncSetAttribute(attn_kernel, cudaFuncAttributeMaxDynamicSharedMemorySize, (int)smem);
    attn_kernel<<<dim3(SEQ / 64, NH, Bsz), 256, smem>>>(mask);

    gemm_nt_kernel<<<gg, 256>>>(pA, Wo, bo, out, 0);
}

// round 10
// speedup vs baseline: 1.3396x; 1.3396x over previous
#include <cuda_runtime.h>
#include <cuda_bf16.h>
#include <math.h>
#include <stdint.h>

#define Bsz 4
#define SEQ 2048
#define DIM 1024
#define NH  16
#define DKH 64
#define MTOT (Bsz*SEQ)   // 8192

// ---- scratch (static device globals: allocation-free) ----
__device__ float g_Q[(size_t)Bsz*NH*SEQ*DKH];   // [B,H,S,DK]
__device__ float g_K[(size_t)Bsz*NH*SEQ*DKH];
__device__ float g_V[(size_t)Bsz*NH*SEQ*DKH];
__device__ float g_A[(size_t)MTOT*DIM];         // attention out, [B,S,D]

// bf16 split buffers (reused serially across the 4 GEMMs)
__device__ __nv_bfloat16 g_ah[(size_t)MTOT*DIM];
__device__ __nv_bfloat16 g_al[(size_t)MTOT*DIM];
__device__ __nv_bfloat16 g_wh[(size_t)DIM*DIM];
__device__ __nv_bfloat16 g_wl[(size_t)DIM*DIM];

// ============================================================
// fp32 -> (bf16 hi, bf16 lo) split, float4-vectorized
// ============================================================
__global__ __launch_bounds__(256)
void split_kernel(const float4* __restrict__ x, uint2* __restrict__ hi,
                  uint2* __restrict__ lo, int n4)
{
    int i = blockIdx.x * 256 + threadIdx.x;
    if (i >= n4) return;
    float4 v = x[i];
    __nv_bfloat16 h0 = __float2bfloat16(v.x);
    __nv_bfloat16 h1 = __float2bfloat16(v.y);
    __nv_bfloat16 h2 = __float2bfloat16(v.z);
    __nv_bfloat16 h3 = __float2bfloat16(v.w);
    __nv_bfloat16 l0 = __float2bfloat16(v.x - __bfloat162float(h0));
    __nv_bfloat16 l1 = __float2bfloat16(v.y - __bfloat162float(h1));
    __nv_bfloat16 l2 = __float2bfloat16(v.z - __bfloat162float(h2));
    __nv_bfloat16 l3 = __float2bfloat16(v.w - __bfloat162float(h3));
    uint2 H, L;
    H.x = (unsigned)__bfloat16_as_ushort(h0) | ((unsigned)__bfloat16_as_ushort(h1) << 16);
    H.y = (unsigned)__bfloat16_as_ushort(h2) | ((unsigned)__bfloat16_as_ushort(h3) << 16);
    L.x = (unsigned)__bfloat16_as_ushort(l0) | ((unsigned)__bfloat16_as_ushort(l1) << 16);
    L.y = (unsigned)__bfloat16_as_ushort(l2) | ((unsigned)__bfloat16_as_ushort(l3) << 16);
    hi[i] = H;
    lo[i] = L;
}

// ============================================================
// warp-mma bf16x3 GEMM: C[M,N] = A[M,K] @ W[N,K]^T + bias
// mma.sync.m16n8k16 (sm_80 baseline PTX -> HMMA on sm_103).
// 128x128 CTA tile, 8 warps (4x2), 32x64 per warp, K-chunk 64.
// ============================================================
#define KC  64
#define LDT 72                       // padded smem stride in bf16 elems
#define OFF_AH 0
#define OFF_AL 18432
#define OFF_BH 36864
#define OFF_BL 55296
#define MM_SMEM 73728

__device__ __forceinline__ uint32_t smem_u32(const void* p) {
    uint32_t a;
    asm("{ .reg .u64 t; cvta.to.shared.u64 t, %1; cvt.u32.u64 %0, t; }" : "=r"(a) : "l"(p));
    return a;
}
__device__ __forceinline__ void ldm4(uint32_t* r, uint32_t addr) {
    asm volatile("ldmatrix.sync.aligned.m8n8.x4.shared.b16 {%0,%1,%2,%3}, [%4];"
                 : "=r"(r[0]), "=r"(r[1]), "=r"(r[2]), "=r"(r[3]) : "r"(addr));
}
__device__ __forceinline__ void ldm2(uint32_t* r, uint32_t addr) {
    asm volatile("ldmatrix.sync.aligned.m8n8.x2.shared.b16 {%0,%1}, [%2];"
                 : "=r"(r[0]), "=r"(r[1]) : "r"(addr));
}
__device__ __forceinline__ void mma_bf16(float* c, const uint32_t* a, const uint32_t* b) {
    asm volatile(
        "mma.sync.aligned.m16n8k16.row.col.f32.bf16.bf16.f32 "
        "{%0,%1,%2,%3}, {%4,%5,%6,%7}, {%8,%9}, {%0,%1,%2,%3};"
        : "+f"(c[0]), "+f"(c[1]), "+f"(c[2]), "+f"(c[3])
        : "r"(a[0]), "r"(a[1]), "r"(a[2]), "r"(a[3]), "r"(b[0]), "r"(b[1]));
}

__global__ __launch_bounds__(256)
void mma_gemm_kernel(const __nv_bfloat16* __restrict__ Ah, const __nv_bfloat16* __restrict__ Al,
                     const __nv_bfloat16* __restrict__ Bh, const __nv_bfloat16* __restrict__ Bl,
                     const float* __restrict__ bias, float* __restrict__ C, int headLayout)
{
    extern __shared__ __align__(16) char smem[];
    const uint32_t sb = smem_u32(smem);
    const int tid = threadIdx.x;
    const int lane = tid & 31, wid = tid >> 5;
    const int wm = wid & 3, wn = wid >> 2;              // 4 (M) x 2 (N) warps
    const int m0 = blockIdx.y * 128, n0 = blockIdx.x * 128;

    float acc[2][8][4];
    #pragma unroll
    for (int mt = 0; mt < 2; mt++)
        #pragma unroll
        for (int nt = 0; nt < 8; nt++)
            #pragma unroll
            for (int c = 0; c < 4; c++) acc[mt][nt][c] = 0.f;

    // per-thread staging indices: 128 rows x 64 bf16 per tile, 8 uint4/row
    const int lr = tid >> 3;            // 0..31 -> rows lr, lr+32, lr+64, lr+96
    const int lc = (tid & 7) * 8;       // bf16 column

    // ldmatrix source addresses (constant across k-chunks except kk offset)
    const uint32_t a_row = (uint32_t)(wm * 32 + (lane & 15));
    const uint32_t a_col = (uint32_t)((lane >> 4) << 3);
    const uint32_t b_row = (uint32_t)(wn * 64 + (lane & 7));
    const uint32_t b_col = (uint32_t)(((lane >> 3) & 1) << 3);

    for (int kc = 0; kc < DIM; kc += KC) {
        // ---- stage 4 tiles: A_hi/A_lo rows m0.., B_hi/B_lo rows n0.. ----
        #pragma unroll
        for (int u = 0; u < 4; ++u) {
            int r = lr + u * 32;
            size_t ga = (size_t)(m0 + r) * DIM + kc + lc;
            size_t gb = (size_t)(n0 + r) * DIM + kc + lc;
            uint32_t so = (uint32_t)(r * LDT + lc) * 2;
            *(uint4*)(smem + OFF_AH + so) = *(const uint4*)(Ah + ga);
            *(uint4*)(smem + OFF_AL + so) = *(const uint4*)(Al + ga);
            *(uint4*)(smem + OFF_BH + so) = *(const uint4*)(Bh + gb);
            *(uint4*)(smem + OFF_BL + so) = *(const uint4*)(Bl + gb);
        }
        __syncthreads();

        #pragma unroll
        for (int kk = 0; kk < KC; kk += 16) {
            uint32_t ahf[2][4], alf[2][4];
            #pragma unroll
            for (int mt = 0; mt < 2; mt++) {
                uint32_t off = ((a_row + mt * 16) * LDT + kk + a_col) * 2;
                ldm4(ahf[mt], sb + OFF_AH + off);
                ldm4(alf[mt], sb + OFF_AL + off);
            }
            #pragma unroll
            for (int nt = 0; nt < 8; nt++) {
                uint32_t boff = ((b_row + nt * 8) * LDT + kk + b_col) * 2;
                uint32_t bh[2], bl[2];
                ldm2(bh, sb + OFF_BH + boff);
                ldm2(bl, sb + OFF_BL + boff);
                #pragma unroll
                for (int mt = 0; mt < 2; mt++) {
                    mma_bf16(acc[mt][nt], ahf[mt], bh);
                    mma_bf16(acc[mt][nt], ahf[mt], bl);
                    mma_bf16(acc[mt][nt], alf[mt], bh);
                }
            }
        }
        __syncthreads();
    }

    // ---- epilogue: c0,c1 -> (row, col..col+1); c2,c3 -> (row+8, ...) ----
    const int row = lane >> 2;
    const int col2 = (lane & 3) * 2;
    #pragma unroll
    for (int nt = 0; nt < 8; nt++) {
        int n = n0 + wn * 64 + nt * 8 + col2;
        float bx = bias[n], by = bias[n + 1];
        #pragma unroll
        for (int mt = 0; mt < 2; mt++) {
            int m = m0 + wm * 32 + mt * 16 + row;
            float* cp0;
            float* cp1;
            if (!headLayout) {
                cp0 = C + (size_t)m * DIM + n;
                cp1 = C + (size_t)(m + 8) * DIM + n;
            } else {
                int h = n >> 6, d0 = n & 63;
                int b_ = m >> 11, s_ = m & 2047;
                float* base = C + (((size_t)(b_ * NH + h) * SEQ + s_) * DKH) + d0;
                cp0 = base;
                cp1 = base + 8 * DKH;      // (m+8) same batch: m%2048 <= 2039 within tile
            }
            float2 v0 = make_float2(acc[mt][nt][0] + bx, acc[mt][nt][1] + by);
            float2 v1 = make_float2(acc[mt][nt][2] + bx, acc[mt][nt][3] + by);
            *(float2*)cp0 = v0;
            *(float2*)cp1 = v1;
        }
    }
}

// ============================================================
// Flash attention (unchanged from passing R4 kernel)
// ============================================================
#define PAD 68
#define SM_Q 0
#define SM_KP (64 * PAD)
#define SM_V  (2 * 64 * PAD)

__global__ __launch_bounds__(256)
void attn_kernel(const int* __restrict__ mask)
{
    extern __shared__ float sm[];
    float* Qts = sm + SM_Q;
    float* KPs = sm + SM_KP;
    float* Vs  = sm + SM_V;

    const int tid = threadIdx.x;
    const int tx = tid & 15, ty = tid >> 4;
    const int q0 = blockIdx.x * 64;
    const int h = blockIdx.y, b = blockIdx.z;

    const float* Qp = g_Q + (((size_t)b * NH + h) * SEQ + q0) * DKH;
    const float* Kb = g_K + (((size_t)b * NH + h) * SEQ) * DKH;
    const float* Vb = g_V + (((size_t)b * NH + h) * SEQ) * DKH;

    #pragma unroll
    for (int u = 0; u < 4; ++u) {
        int f = tid + u * 256;
        int r = f >> 4, d4 = (f & 15) << 2;
        float4 v = *(const float4*)(Qp + r * DKH + d4);
        Qts[(d4+0)*PAD + r] = v.x; Qts[(d4+1)*PAD + r] = v.y;
        Qts[(d4+2)*PAD + r] = v.z; Qts[(d4+3)*PAD + r] = v.w;
    }

    float Ot[4][4];
    #pragma unroll
    for (int i = 0; i < 4; i++)
        #pragma unroll
        for (int j = 0; j < 4; j++) Ot[i][j] = 0.f;
    float mi[4] = {-1e30f, -1e30f, -1e30f, -1e30f};
    float li[4] = {0.f, 0.f, 0.f, 0.f};

    const int* mrow = mask + ((size_t)b * SEQ + q0 + ty * 4) * SEQ;

    for (int k0 = 0; k0 < SEQ; k0 += 64) {
        #pragma unroll
        for (int u = 0; u < 4; ++u) {
            int f = tid + u * 256;
            int r = f >> 4, d4 = (f & 15) << 2;
            float4 kv = *(const float4*)(Kb + (size_t)(k0 + r) * DKH + d4);
            KPs[(d4+0)*PAD + r] = kv.x; KPs[(d4+1)*PAD + r] = kv.y;
            KPs[(d4+2)*PAD + r] = kv.z; KPs[(d4+3)*PAD + r] = kv.w;
            float4 vv = *(const float4*)(Vb + (size_t)(k0 + r) * DKH + d4);
            *(float4*)&Vs[r * PAD + d4] = vv;
        }
        __syncthreads();

        float s[4][4];
        #pragma unroll
        for (int i = 0; i < 4; i++)
            #pragma unroll
            for (int j = 0; j < 4; j++) s[i][j] = 0.f;
        #pragma unroll 16
        for (int d = 0; d < 64; ++d) {
            float4 qa = *(const float4*)&Qts[d * PAD + ty * 4];
            float4 kb = *(const float4*)&KPs[d * PAD + tx * 4];
            float qr[4] = {qa.x, qa.y, qa.z, qa.w};
            float kr[4] = {kb.x, kb.y, kb.z, kb.w};
            #pragma unroll
            for (int i = 0; i < 4; i++)
                #pragma unroll
                for (int j = 0; j < 4; j++)
                    s[i][j] = fmaf(qr[i], kr[j], s[i][j]);
        }

        #pragma unroll
        for (int i = 0; i < 4; i++) {
            const int4 mk = *(const int4*)(mrow + (size_t)i * SEQ + k0 + tx * 4);
            s[i][0] = mk.x ? s[i][0] * 0.125f : -1e9f;
            s[i][1] = mk.y ? s[i][1] * 0.125f : -1e9f;
            s[i][2] = mk.z ? s[i][2] * 0.125f : -1e9f;
            s[i][3] = mk.w ? s[i][3] * 0.125f : -1e9f;

            float mx = fmaxf(fmaxf(s[i][0], s[i][1]), fmaxf(s[i][2], s[i][3]));
            #pragma unroll
            for (int o = 8; o > 0; o >>= 1)
                mx = fmaxf(mx, __shfl_xor_sync(0xffffffffu, mx, o));
            float mn = fmaxf(mi[i], mx);
            float corr = __expf(mi[i] - mn);
            mi[i] = mn;
            float rs = 0.f;
            #pragma unroll
            for (int j = 0; j < 4; j++) {
                s[i][j] = __expf(s[i][j] - mn);
                rs += s[i][j];
            }
            #pragma unroll
            for (int o = 8; o > 0; o >>= 1)
                rs += __shfl_xor_sync(0xffffffffu, rs, o);
            li[i] = li[i] * corr + rs;
            #pragma unroll
            for (int j = 0; j < 4; j++) Ot[i][j] *= corr;
        }
        __syncthreads();

        #pragma unroll
        for (int i = 0; i < 4; i++)
            *(float4*)&KPs[(ty * 4 + i) * PAD + tx * 4] =
                make_float4(s[i][0], s[i][1], s[i][2], s[i][3]);
        __syncthreads();

        #pragma unroll 8
        for (int c = 0; c < 64; ++c) {
            float4 vv = *(const float4*)&Vs[c * PAD + tx * 4];
            float p0 = KPs[(ty * 4 + 0) * PAD + c];
            float p1 = KPs[(ty * 4 + 1) * PAD + c];
            float p2 = KPs[(ty * 4 + 2) * PAD + c];
            float p3 = KPs[(ty * 4 + 3) * PAD + c];
            Ot[0][0] = fmaf(p0, vv.x, Ot[0][0]); Ot[0][1] = fmaf(p0, vv.y, Ot[0][1]);
            Ot[0][2] = fmaf(p0, vv.z, Ot[0][2]); Ot[0][3] = fmaf(p0, vv.w, Ot[0][3]);
            Ot[1][0] = fmaf(p1, vv.x, Ot[1][0]); Ot[1][1] = fmaf(p1, vv.y, Ot[1][1]);
            Ot[1][2] = fmaf(p1, vv.z, Ot[1][2]); Ot[1][3] = fmaf(p1, vv.w, Ot[1][3]);
            Ot[2][0] = fmaf(p2, vv.x, Ot[2][0]); Ot[2][1] = fmaf(p2, vv.y, Ot[2][1]);
            Ot[2][2] = fmaf(p2, vv.z, Ot[2][2]); Ot[2][3] = fmaf(p2, vv.w, Ot[2][3]);
            Ot[3][0] = fmaf(p3, vv.x, Ot[3][0]); Ot[3][1] = fmaf(p3, vv.y, Ot[3][1]);
            Ot[3][2] = fmaf(p3, vv.z, Ot[3][2]); Ot[3][3] = fmaf(p3, vv.w, Ot[3][3]);
        }
        __syncthreads();
    }

    #pragma unroll
    for (int i = 0; i < 4; i++) {
        float inv = 1.f / li[i];
        float* op = g_A + ((size_t)b * SEQ + q0 + ty * 4 + i) * DIM + h * DKH + tx * 4;
        *(float4*)op = make_float4(Ot[i][0]*inv, Ot[i][1]*inv, Ot[i][2]*inv, Ot[i][3]*inv);
    }
}

// ============================================================
extern "C" void kernel_launch(void* const* d_in, const int* in_sizes, int n_in,
                              void* d_out, int out_size)
{
    const float* q    = (const float*)d_in[0];
    const float* k    = (const float*)d_in[1];
    const float* v    = (const float*)d_in[2];
    const int*   mask = (const int*)  d_in[3];
    const float* Wq   = (const float*)d_in[4];
    const float* bq   = (const float*)d_in[5];
    const float* Wk   = (const float*)d_in[6];
    const float* bk   = (const float*)d_in[7];
    const float* Wv   = (const float*)d_in[8];
    const float* bv   = (const float*)d_in[9];
    const float* Wo   = (const float*)d_in[10];
    const float* bo   = (const float*)d_in[11];
    float* out = (float*)d_out;

    float *pQ, *pK, *pV, *pA;
    __nv_bfloat16 *pah, *pal, *pwh, *pwl;
    cudaGetSymbolAddress((void**)&pQ, g_Q);
    cudaGetSymbolAddress((void**)&pK, g_K);
    cudaGetSymbolAddress((void**)&pV, g_V);
    cudaGetSymbolAddress((void**)&pA, g_A);
    cudaGetSymbolAddress((void**)&pah, g_ah);
    cudaGetSymbolAddress((void**)&pal, g_al);
    cudaGetSymbolAddress((void**)&pwh, g_wh);
    cudaGetSymbolAddress((void**)&pwl, g_wl);

    cudaFuncSetAttribute(mma_gemm_kernel, cudaFuncAttributeMaxDynamicSharedMemorySize, MM_SMEM);
    size_t attn_smem = 3 * 64 * PAD * sizeof(float);
    cudaFuncSetAttribute(attn_kernel, cudaFuncAttributeMaxDynamicSharedMemorySize, (int)attn_smem);

    const int n4_act = MTOT * DIM / 4;   // 2,097,152
    const int n4_w   = DIM * DIM / 4;    // 262,144
    dim3 gg(DIM / 128, MTOT / 128);      // (8, 64)

    // Q projection
    split_kernel<<<n4_act / 256, 256>>>((const float4*)q, (uint2*)pah, (uint2*)pal, n4_act);
    split_kernel<<<n4_w / 256, 256>>>((const float4*)Wq, (uint2*)pwh, (uint2*)pwl, n4_w);
    mma_gemm_kernel<<<gg, 256, MM_SMEM>>>(pah, pal, pwh, pwl, bq, pQ, 1);
    // K projection
    split_kernel<<<n4_act / 256, 256>>>((const float4*)k, (uint2*)pah, (uint2*)pal, n4_act);
    split_kernel<<<n4_w / 256, 256>>>((const float4*)Wk, (uint2*)pwh, (uint2*)pwl, n4_w);
    mma_gemm_kernel<<<gg, 256, MM_SMEM>>>(pah, pal, pwh, pwl, bk, pK, 1);
    // V projection
    split_kernel<<<n4_act / 256, 256>>>((const float4*)v, (uint2*)pah, (uint2*)pal, n4_act);
    split_kernel<<<n4_w / 256, 256>>>((const float4*)Wv, (uint2*)pwh, (uint2*)pwl, n4_w);
    mma_gemm_kernel<<<gg, 256, MM_SMEM>>>(pah, pal, pwh, pwl, bv, pV, 1);

    // attention
    attn_kernel<<<dim3(SEQ / 64, NH, Bsz), 256, attn_smem>>>(mask);

    // output projection
    split_kernel<<<n4_act / 256, 256>>>((const float4*)pA, (uint2*)pah, (uint2*)pal, n4_act);
    split_kernel<<<n4_w / 256, 256>>>((const float4*)Wo, (uint2*)pwh, (uint2*)pwl, n4_w);
    mma_gemm_kernel<<<gg, 256, MM_SMEM>>>(pah, pal, pwh, pwl, bo, out, 0);
}

// round 11
// speedup vs baseline: 2.2215x; 1.6583x over previous
#include <cuda_runtime.h>
#include <cuda_bf16.h>
#include <math.h>
#include <stdint.h>

#define Bsz 4
#define SEQ 2048
#define DIM 1024
#define NH  16
#define DKH 64
#define MTOT (Bsz*SEQ)   // 8192

// ---- scratch (static device globals: allocation-free) ----
__device__ float g_Q[(size_t)Bsz*NH*SEQ*DKH];   // [B,H,S,DK]
__device__ float g_K[(size_t)Bsz*NH*SEQ*DKH];
__device__ float g_V[(size_t)Bsz*NH*SEQ*DKH];
__device__ float g_A[(size_t)MTOT*DIM];         // attention out, [B,S,D]

// bf16 split buffers (reused serially across the 4 GEMMs)
__device__ __nv_bfloat16 g_ah[(size_t)MTOT*DIM];
__device__ __nv_bfloat16 g_al[(size_t)MTOT*DIM];
__device__ __nv_bfloat16 g_wh[(size_t)DIM*DIM];
__device__ __nv_bfloat16 g_wl[(size_t)DIM*DIM];

// ============================================================
// common helpers
// ============================================================
__device__ __forceinline__ uint32_t smem_u32(const void* p) {
    uint32_t a;
    asm("{ .reg .u64 t; cvta.to.shared.u64 t, %1; cvt.u32.u64 %0, t; }" : "=r"(a) : "l"(p));
    return a;
}
__device__ __forceinline__ void ldm4(uint32_t* r, uint32_t addr) {
    asm volatile("ldmatrix.sync.aligned.m8n8.x4.shared.b16 {%0,%1,%2,%3}, [%4];"
                 : "=r"(r[0]), "=r"(r[1]), "=r"(r[2]), "=r"(r[3]) : "r"(addr));
}
__device__ __forceinline__ void ldm2(uint32_t* r, uint32_t addr) {
    asm volatile("ldmatrix.sync.aligned.m8n8.x2.shared.b16 {%0,%1}, [%2];"
                 : "=r"(r[0]), "=r"(r[1]) : "r"(addr));
}
__device__ __forceinline__ void ldm2t(uint32_t* r, uint32_t addr) {
    asm volatile("ldmatrix.sync.aligned.m8n8.x2.trans.shared.b16 {%0,%1}, [%2];"
                 : "=r"(r[0]), "=r"(r[1]) : "r"(addr));
}
__device__ __forceinline__ void mma_bf16(float* c, const uint32_t* a, const uint32_t* b) {
    asm volatile(
        "mma.sync.aligned.m16n8k16.row.col.f32.bf16.bf16.f32 "
        "{%0,%1,%2,%3}, {%4,%5,%6,%7}, {%8,%9}, {%0,%1,%2,%3};"
        : "+f"(c[0]), "+f"(c[1]), "+f"(c[2]), "+f"(c[3])
        : "r"(a[0]), "r"(a[1]), "r"(a[2]), "r"(a[3]), "r"(b[0]), "r"(b[1]));
}
// pack 2 floats to bf16x2 (x -> low, y -> high) hi/lo split
__device__ __forceinline__ void split2(float x, float y, uint32_t& H, uint32_t& L) {
    __nv_bfloat16 hx = __float2bfloat16(x), hy = __float2bfloat16(y);
    float lx = x - __bfloat162float(hx), ly = y - __bfloat162float(hy);
    __nv_bfloat16 lxb = __float2bfloat16(lx), lyb = __float2bfloat16(ly);
    H = (uint32_t)__bfloat16_as_ushort(hx) | ((uint32_t)__bfloat16_as_ushort(hy) << 16);
    L = (uint32_t)__bfloat16_as_ushort(lxb) | ((uint32_t)__bfloat16_as_ushort(lyb) << 16);
}
__device__ __forceinline__ void split4(float4 v, uint2& H, uint2& L) {
    split2(v.x, v.y, H.x, L.x);
    split2(v.z, v.w, H.y, L.y);
}

// ============================================================
// fp32 -> (bf16 hi, bf16 lo) split, float4-vectorized
// ============================================================
__global__ __launch_bounds__(256)
void split_kernel(const float4* __restrict__ x, uint2* __restrict__ hi,
                  uint2* __restrict__ lo, int n4)
{
    int i = blockIdx.x * 256 + threadIdx.x;
    if (i >= n4) return;
    uint2 H, L;
    split4(x[i], H, L);
    hi[i] = H;
    lo[i] = L;
}

// ============================================================
// warp-mma bf16x3 GEMM: C[M,N] = A[M,K] @ W[N,K]^T + bias
// (unchanged from R10 passing kernel)
// ============================================================
#define KC  64
#define LDT 72
#define OFF_AH 0
#define OFF_AL 18432
#define OFF_BH 36864
#define OFF_BL 55296
#define MM_SMEM 73728

__global__ __launch_bounds__(256)
void mma_gemm_kernel(const __nv_bfloat16* __restrict__ Ah, const __nv_bfloat16* __restrict__ Al,
                     const __nv_bfloat16* __restrict__ Bh, const __nv_bfloat16* __restrict__ Bl,
                     const float* __restrict__ bias, float* __restrict__ C, int headLayout)
{
    extern __shared__ __align__(16) char smem[];
    const uint32_t sb = smem_u32(smem);
    const int tid = threadIdx.x;
    const int lane = tid & 31, wid = tid >> 5;
    const int wm = wid & 3, wn = wid >> 2;
    const int m0 = blockIdx.y * 128, n0 = blockIdx.x * 128;

    float acc[2][8][4];
    #pragma unroll
    for (int mt = 0; mt < 2; mt++)
        #pragma unroll
        for (int nt = 0; nt < 8; nt++)
            #pragma unroll
            for (int c = 0; c < 4; c++) acc[mt][nt][c] = 0.f;

    const int lr = tid >> 3;
    const int lc = (tid & 7) * 8;

    const uint32_t a_row = (uint32_t)(wm * 32 + (lane & 15));
    const uint32_t a_col = (uint32_t)((lane >> 4) << 3);
    const uint32_t b_row = (uint32_t)(wn * 64 + (lane & 7));
    const uint32_t b_col = (uint32_t)(((lane >> 3) & 1) << 3);

    for (int kc = 0; kc < DIM; kc += KC) {
        #pragma unroll
        for (int u = 0; u < 4; ++u) {
            int r = lr + u * 32;
            size_t ga = (size_t)(m0 + r) * DIM + kc + lc;
            size_t gb = (size_t)(n0 + r) * DIM + kc + lc;
            uint32_t so = (uint32_t)(r * LDT + lc) * 2;
            *(uint4*)(smem + OFF_AH + so) = *(const uint4*)(Ah + ga);
            *(uint4*)(smem + OFF_AL + so) = *(const uint4*)(Al + ga);
            *(uint4*)(smem + OFF_BH + so) = *(const uint4*)(Bh + gb);
            *(uint4*)(smem + OFF_BL + so) = *(const uint4*)(Bl + gb);
        }
        __syncthreads();

        #pragma unroll
        for (int kk = 0; kk < KC; kk += 16) {
            uint32_t ahf[2][4], alf[2][4];
            #pragma unroll
            for (int mt = 0; mt < 2; mt++) {
                uint32_t off = ((a_row + mt * 16) * LDT + kk + a_col) * 2;
                ldm4(ahf[mt], sb + OFF_AH + off);
                ldm4(alf[mt], sb + OFF_AL + off);
            }
            #pragma unroll
            for (int nt = 0; nt < 8; nt++) {
                uint32_t boff = ((b_row + nt * 8) * LDT + kk + b_col) * 2;
                uint32_t bh[2], bl[2];
                ldm2(bh, sb + OFF_BH + boff);
                ldm2(bl, sb + OFF_BL + boff);
                #pragma unroll
                for (int mt = 0; mt < 2; mt++) {
                    mma_bf16(acc[mt][nt], ahf[mt], bh);
                    mma_bf16(acc[mt][nt], ahf[mt], bl);
                    mma_bf16(acc[mt][nt], alf[mt], bh);
                }
            }
        }
        __syncthreads();
    }

    const int row = lane >> 2;
    const int col2 = (lane & 3) * 2;
    #pragma unroll
    for (int nt = 0; nt < 8; nt++) {
        int n = n0 + wn * 64 + nt * 8 + col2;
        float bx = bias[n], by = bias[n + 1];
        #pragma unroll
        for (int mt = 0; mt < 2; mt++) {
            int m = m0 + wm * 32 + mt * 16 + row;
            float *cp0, *cp1;
            if (!headLayout) {
                cp0 = C + (size_t)m * DIM + n;
                cp1 = C + (size_t)(m + 8) * DIM + n;
            } else {
                int h = n >> 6, d0 = n & 63;
                int b_ = m >> 11, s_ = m & 2047;
                float* base = C + (((size_t)(b_ * NH + h) * SEQ + s_) * DKH) + d0;
                cp0 = base;
                cp1 = base + 8 * DKH;
            }
            *(float2*)cp0 = make_float2(acc[mt][nt][0] + bx, acc[mt][nt][1] + by);
            *(float2*)cp1 = make_float2(acc[mt][nt][2] + bx, acc[mt][nt][3] + by);
        }
    }
}

// ============================================================
// Tensor-core flash attention (bf16x3 on QK^T and PV)
// CTA: 128 q-rows of one (b,h). 8 warps, 16 q-rows each.
// smem: Kh/Kl/Vh/Vl tiles 64 x 72 bf16 (Q staged here first).
// ============================================================
#define ALD 72
#define SKH 0
#define SKL 9216
#define SVH 18432
#define SVL 27648
#define AT_SMEM 36864

__global__ __launch_bounds__(256, 1)
void attn_mma_kernel(const int* __restrict__ mask)
{
    extern __shared__ __align__(16) char sm[];
    const uint32_t sb = smem_u32(sm);
    const int tid = threadIdx.x, lane = tid & 31, wid = tid >> 5;
    const int q0 = blockIdx.x * 128;
    const int h = blockIdx.y, b = blockIdx.z;

    const float* Qp = g_Q + (((size_t)b * NH + h) * SEQ + q0) * DKH;
    const float* Kb = g_K + (((size_t)b * NH + h) * SEQ) * DKH;
    const float* Vb = g_V + (((size_t)b * NH + h) * SEQ) * DKH;

    // ---- stage Q (pre-scaled by 1/8), split, into smem; then -> register fragments ----
    #pragma unroll
    for (int u = 0; u < 8; ++u) {
        int f = tid + u * 256;              // 0..2047
        int r = f >> 4, c4 = (f & 15) << 2;
        float4 v = *(const float4*)(Qp + r * DKH + c4);
        v.x *= 0.125f; v.y *= 0.125f; v.z *= 0.125f; v.w *= 0.125f;
        uint2 H, L;
        split4(v, H, L);
        uint32_t so = (uint32_t)(r * ALD + c4) * 2;
        *(uint2*)(sm + so) = H;             // Qh region [0, 18432)
        *(uint2*)(sm + 18432 + so) = L;     // Ql region [18432, 36864)
    }
    __syncthreads();

    uint32_t qh[4][4], ql[4][4];
    {
        const uint32_t a_row = (uint32_t)(wid * 16 + (lane & 15));
        const uint32_t a_col = (uint32_t)((lane >> 4) << 3);
        #pragma unroll
        for (int kk = 0; kk < 4; ++kk) {
            uint32_t off = (a_row * ALD + kk * 16 + a_col) * 2;
            ldm4(qh[kk], sb + off);
            ldm4(ql[kk], sb + 18432 + off);
        }
    }
    __syncthreads();    // smem now free for K/V tiles

    float oacc[8][4];
    #pragma unroll
    for (int nt = 0; nt < 8; nt++)
        #pragma unroll
        for (int c = 0; c < 4; c++) oacc[nt][c] = 0.f;
    float mi0 = -1e30f, mi1 = -1e30f, li0 = 0.f, li1 = 0.f;

    const int row0 = wid * 16 + (lane >> 2);
    const int col2 = (lane & 3) * 2;
    const int* mrow0 = mask + ((size_t)b * SEQ + q0 + row0) * SEQ + col2;
    const int* mrow1 = mrow0 + 8 * SEQ;

    const uint32_t kb_row = (uint32_t)(lane & 7);
    const uint32_t kb_col = (uint32_t)(((lane >> 3) & 1) << 3);
    const uint32_t v_row = (uint32_t)(lane & 15);

    for (int k0 = 0; k0 < SEQ; k0 += 64) {
        // ---- stage K, V tiles (64x64 fp32 -> bf16 hi/lo, row-major) ----
        #pragma unroll
        for (int u = 0; u < 4; ++u) {
            int f = tid + u * 256;          // 0..1023
            int r = f >> 4, c4 = (f & 15) << 2;
            uint32_t so = (uint32_t)(r * ALD + c4) * 2;
            uint2 H, L;
            split4(*(const float4*)(Kb + (size_t)(k0 + r) * DKH + c4), H, L);
            *(uint2*)(sm + SKH + so) = H;
            *(uint2*)(sm + SKL + so) = L;
            split4(*(const float4*)(Vb + (size_t)(k0 + r) * DKH + c4), H, L);
            *(uint2*)(sm + SVH + so) = H;
            *(uint2*)(sm + SVL + so) = L;
        }
        __syncthreads();

        // ---- S = Q K^T (bf16x3) ----
        float sacc[8][4];
        #pragma unroll
        for (int nt = 0; nt < 8; nt++)
            #pragma unroll
            for (int c = 0; c < 4; c++) sacc[nt][c] = 0.f;
        #pragma unroll
        for (int kk = 0; kk < 4; ++kk) {
            #pragma unroll
            for (int nt = 0; nt < 8; nt++) {
                uint32_t off = ((nt * 8 + kb_row) * ALD + kk * 16 + kb_col) * 2;
                uint32_t bh[2], bl[2];
                ldm2(bh, sb + SKH + off);
                ldm2(bl, sb + SKL + off);
                mma_bf16(sacc[nt], qh[kk], bh);
                mma_bf16(sacc[nt], qh[kk], bl);
                mma_bf16(sacc[nt], ql[kk], bh);
            }
        }

        // ---- mask + online softmax ----
        float mx0 = -1e30f, mx1 = -1e30f;
        #pragma unroll
        for (int nt = 0; nt < 8; nt++) {
            int2 m0 = *(const int2*)(mrow0 + k0 + nt * 8);
            int2 m1 = *(const int2*)(mrow1 + k0 + nt * 8);
            sacc[nt][0] = m0.x ? sacc[nt][0] : -1e9f;
            sacc[nt][1] = m0.y ? sacc[nt][1] : -1e9f;
            sacc[nt][2] = m1.x ? sacc[nt][2] : -1e9f;
            sacc[nt][3] = m1.y ? sacc[nt][3] : -1e9f;
            mx0 = fmaxf(mx0, fmaxf(sacc[nt][0], sacc[nt][1]));
            mx1 = fmaxf(mx1, fmaxf(sacc[nt][2], sacc[nt][3]));
        }
        #pragma unroll
        for (int o = 1; o <= 2; o <<= 1) {
            mx0 = fmaxf(mx0, __shfl_xor_sync(0xffffffffu, mx0, o));
            mx1 = fmaxf(mx1, __shfl_xor_sync(0xffffffffu, mx1, o));
        }
        float mn0 = fmaxf(mi0, mx0), mn1 = fmaxf(mi1, mx1);
        float corr0 = __expf(mi0 - mn0), corr1 = __expf(mi1 - mn1);
        mi0 = mn0; mi1 = mn1;

        float rs0 = 0.f, rs1 = 0.f;
        #pragma unroll
        for (int nt = 0; nt < 8; nt++) {
            sacc[nt][0] = __expf(sacc[nt][0] - mn0);
            sacc[nt][1] = __expf(sacc[nt][1] - mn0);
            sacc[nt][2] = __expf(sacc[nt][2] - mn1);
            sacc[nt][3] = __expf(sacc[nt][3] - mn1);
            rs0 += sacc[nt][0] + sacc[nt][1];
            rs1 += sacc[nt][2] + sacc[nt][3];
        }
        #pragma unroll
        for (int o = 1; o <= 2; o <<= 1) {
            rs0 += __shfl_xor_sync(0xffffffffu, rs0, o);
            rs1 += __shfl_xor_sync(0xffffffffu, rs1, o);
        }
        li0 = li0 * corr0 + rs0;
        li1 = li1 * corr1 + rs1;
        #pragma unroll
        for (int nt = 0; nt < 8; nt++) {
            oacc[nt][0] *= corr0; oacc[nt][1] *= corr0;
            oacc[nt][2] *= corr1; oacc[nt][3] *= corr1;
        }

        // ---- P fragments (bf16 hi/lo) straight from S accumulators ----
        uint32_t ph[4][4], pl[4][4];
        #pragma unroll
        for (int kt = 0; kt < 4; ++kt) {
            split2(sacc[2*kt][0],   sacc[2*kt][1],   ph[kt][0], pl[kt][0]);
            split2(sacc[2*kt][2],   sacc[2*kt][3],   ph[kt][1], pl[kt][1]);
            split2(sacc[2*kt+1][0], sacc[2*kt+1][1], ph[kt][2], pl[kt][2]);
            split2(sacc[2*kt+1][2], sacc[2*kt+1][3], ph[kt][3], pl[kt][3]);
        }

        // ---- O += P V (bf16x3, V via ldmatrix.trans) ----
        #pragma unroll
        for (int kt = 0; kt < 4; ++kt) {
            #pragma unroll
            for (int nd = 0; nd < 8; nd++) {
                uint32_t off = ((kt * 16 + v_row) * ALD + nd * 8) * 2;
                uint32_t vh[2], vl[2];
                ldm2t(vh, sb + SVH + off);
                ldm2t(vl, sb + SVL + off);
                mma_bf16(oacc[nd], ph[kt], vh);
                mma_bf16(oacc[nd], ph[kt], vl);
                mma_bf16(oacc[nd], pl[kt], vh);
            }
        }
        __syncthreads();    // before next tile overwrites K/V smem
    }

    // ---- normalize + write g_A[b][q][h*64 + d] ----
    float inv0 = 1.f / li0, inv1 = 1.f / li1;
    float* op0 = g_A + ((size_t)b * SEQ + q0 + row0) * DIM + h * DKH + col2;
    float* op1 = op0 + 8 * DIM;
    #pragma unroll
    for (int nd = 0; nd < 8; nd++) {
        *(float2*)(op0 + nd * 8) = make_float2(oacc[nd][0] * inv0, oacc[nd][1] * inv0);
        *(float2*)(op1 + nd * 8) = make_float2(oacc[nd][2] * inv1, oacc[nd][3] * inv1);
    }
}

// ============================================================
extern "C" void kernel_launch(void* const* d_in, const int* in_sizes, int n_in,
                              void* d_out, int out_size)
{
    const float* q    = (const float*)d_in[0];
    const float* k    = (const float*)d_in[1];
    const float* v    = (const float*)d_in[2];
    const int*   mask = (const int*)  d_in[3];
    const float* Wq   = (const float*)d_in[4];
    const float* bq   = (const float*)d_in[5];
    const float* Wk   = (const float*)d_in[6];
    const float* bk   = (const float*)d_in[7];
    const float* Wv   = (const float*)d_in[8];
    const float* bv   = (const float*)d_in[9];
    const float* Wo   = (const float*)d_in[10];
    const float* bo   = (const float*)d_in[11];
    float* out = (float*)d_out;

    float *pQ, *pK, *pV, *pA;
    __nv_bfloat16 *pah, *pal, *pwh, *pwl;
    cudaGetSymbolAddress((void**)&pQ, g_Q);
    cudaGetSymbolAddress((void**)&pK, g_K);
    cudaGetSymbolAddress((void**)&pV, g_V);
    cudaGetSymbolAddress((void**)&pA, g_A);
    cudaGetSymbolAddress((void**)&pah, g_ah);
    cudaGetSymbolAddress((void**)&pal, g_al);
    cudaGetSymbolAddress((void**)&pwh, g_wh);
    cudaGetSymbolAddress((void**)&pwl, g_wl);

    cudaFuncSetAttribute(mma_gemm_kernel, cudaFuncAttributeMaxDynamicSharedMemorySize, MM_SMEM);
    cudaFuncSetAttribute(attn_mma_kernel, cudaFuncAttributeMaxDynamicSharedMemorySize, AT_SMEM);

    const int n4_act = MTOT * DIM / 4;
    const int n4_w   = DIM * DIM / 4;
    dim3 gg(DIM / 128, MTOT / 128);

    // Q projection
    split_kernel<<<n4_act / 256, 256>>>((const float4*)q, (uint2*)pah, (uint2*)pal, n4_act);
    split_kernel<<<n4_w / 256, 256>>>((const float4*)Wq, (uint2*)pwh, (uint2*)pwl, n4_w);
    mma_gemm_kernel<<<gg, 256, MM_SMEM>>>(pah, pal, pwh, pwl, bq, pQ, 1);
    // K projection
    split_kernel<<<n4_act / 256, 256>>>((const float4*)k, (uint2*)pah, (uint2*)pal, n4_act);
    split_kernel<<<n4_w / 256, 256>>>((const float4*)Wk, (uint2*)pwh, (uint2*)pwl, n4_w);
    mma_gemm_kernel<<<gg, 256, MM_SMEM>>>(pah, pal, pwh, pwl, bk, pK, 1);
    // V projection
    split_kernel<<<n4_act / 256, 256>>>((const float4*)v, (uint2*)pah, (uint2*)pal, n4_act);
    split_kernel<<<n4_w / 256, 256>>>((const float4*)Wv, (uint2*)pwh, (uint2*)pwl, n4_w);
    mma_gemm_kernel<<<gg, 256, MM_SMEM>>>(pah, pal, pwh, pwl, bv, pV, 1);

    // attention (tensor-core flash)
    attn_mma_kernel<<<dim3(SEQ / 128, NH, Bsz), 256, AT_SMEM>>>(mask);

    // output projection
    split_kernel<<<n4_act / 256, 256>>>((const float4*)pA, (uint2*)pah, (uint2*)pal, n4_act);
    split_kernel<<<n4_w / 256, 256>>>((const float4*)Wo, (uint2*)pwh, (uint2*)pwl, n4_w);
    mma_gemm_kernel<<<gg, 256, MM_SMEM>>>(pah, pal, pwh, pwl, bo, out, 0);
}

// round 12
// speedup vs baseline: 2.5170x; 1.1330x over previous
#include <cuda_runtime.h>
#include <cuda_bf16.h>
#include <math.h>
#include <stdint.h>

#define Bsz 4
#define SEQ 2048
#define DIM 1024
#define NH  16
#define DKH 64
#define MTOT (Bsz*SEQ)   // 8192

// ---- scratch (static device globals: allocation-free) ----
// A-side split buffers (also receive attention output split)
__device__ __nv_bfloat16 g_ah[(size_t)MTOT*DIM];
__device__ __nv_bfloat16 g_al[(size_t)MTOT*DIM];
// weight split buffers
__device__ __nv_bfloat16 g_wh[(size_t)DIM*DIM];
__device__ __nv_bfloat16 g_wl[(size_t)DIM*DIM];
// projected Q/K/V in bf16 hi/lo, [B,H,S,DK] (Q pre-scaled by 0.125)
__device__ __nv_bfloat16 g_Qh[(size_t)MTOT*DIM];
__device__ __nv_bfloat16 g_Ql[(size_t)MTOT*DIM];
__device__ __nv_bfloat16 g_Kh[(size_t)MTOT*DIM];
__device__ __nv_bfloat16 g_Kl[(size_t)MTOT*DIM];
__device__ __nv_bfloat16 g_Vh[(size_t)MTOT*DIM];
__device__ __nv_bfloat16 g_Vl[(size_t)MTOT*DIM];

// ============================================================
// common helpers
// ============================================================
__device__ __forceinline__ uint32_t smem_u32(const void* p) {
    uint32_t a;
    asm("{ .reg .u64 t; cvta.to.shared.u64 t, %1; cvt.u32.u64 %0, t; }" : "=r"(a) : "l"(p));
    return a;
}
__device__ __forceinline__ void ldm4(uint32_t* r, uint32_t addr) {
    asm volatile("ldmatrix.sync.aligned.m8n8.x4.shared.b16 {%0,%1,%2,%3}, [%4];"
                 : "=r"(r[0]), "=r"(r[1]), "=r"(r[2]), "=r"(r[3]) : "r"(addr));
}
__device__ __forceinline__ void ldm4t(uint32_t* r, uint32_t addr) {
    asm volatile("ldmatrix.sync.aligned.m8n8.x4.trans.shared.b16 {%0,%1,%2,%3}, [%4];"
                 : "=r"(r[0]), "=r"(r[1]), "=r"(r[2]), "=r"(r[3]) : "r"(addr));
}
__device__ __forceinline__ void mma_bf16(float* c, const uint32_t* a, const uint32_t* b) {
    asm volatile(
        "mma.sync.aligned.m16n8k16.row.col.f32.bf16.bf16.f32 "
        "{%0,%1,%2,%3}, {%4,%5,%6,%7}, {%8,%9}, {%0,%1,%2,%3};"
        : "+f"(c[0]), "+f"(c[1]), "+f"(c[2]), "+f"(c[3])
        : "r"(a[0]), "r"(a[1]), "r"(a[2]), "r"(a[3]), "r"(b[0]), "r"(b[1]));
}
__device__ __forceinline__ void split2(float x, float y, uint32_t& H, uint32_t& L) {
    __nv_bfloat16 hx = __float2bfloat16(x), hy = __float2bfloat16(y);
    float lx = x - __bfloat162float(hx), ly = y - __bfloat162float(hy);
    __nv_bfloat16 lxb = __float2bfloat16(lx), lyb = __float2bfloat16(ly);
    H = (uint32_t)__bfloat16_as_ushort(hx) | ((uint32_t)__bfloat16_as_ushort(hy) << 16);
    L = (uint32_t)__bfloat16_as_ushort(lxb) | ((uint32_t)__bfloat16_as_ushort(lyb) << 16);
}
__device__ __forceinline__ void split4(float4 v, uint2& H, uint2& L) {
    split2(v.x, v.y, H.x, L.x);
    split2(v.z, v.w, H.y, L.y);
}
__device__ __forceinline__ void cp16(uint32_t dst, const void* src) {
    asm volatile("cp.async.cg.shared.global [%0], [%1], 16;" :: "r"(dst), "l"(src));
}
__device__ __forceinline__ void cp_commit() {
    asm volatile("cp.async.commit_group;" ::: "memory");
}
template<int N> __device__ __forceinline__ void cp_wait() {
    asm volatile("cp.async.wait_group %0;" :: "n"(N) : "memory");
}

// ============================================================
// fp32 -> (bf16 hi, bf16 lo) split, float4-vectorized
// ============================================================
__global__ __launch_bounds__(256)
void split_kernel(const float4* __restrict__ x, uint2* __restrict__ hi,
                  uint2* __restrict__ lo, int n4)
{
    int i = blockIdx.x * 256 + threadIdx.x;
    if (i >= n4) return;
    uint2 H, L;
    split4(x[i], H, L);
    hi[i] = H;
    lo[i] = L;
}

// ============================================================
// warp-mma bf16x3 GEMM, cp.async double-buffered.
// C = A[M,K] @ W[N,K]^T + bias
// mode 0: fp32 out [M,N]
// mode 1: bf16 hi/lo out, head layout [B,H,S,DK], scaled
// ============================================================
#define KC  64
#define NCH (DIM/KC)     // 16
#define LDT 72
#define OFF_AH 0
#define OFF_AL 18432
#define OFF_BH 36864
#define OFF_BL 55296
#define STG    73728
#define MM_SMEM (2*STG)  // 147456

__global__ __launch_bounds__(256, 1)
void mma_gemm_kernel(const __nv_bfloat16* __restrict__ Ah, const __nv_bfloat16* __restrict__ Al,
                     const __nv_bfloat16* __restrict__ Bh, const __nv_bfloat16* __restrict__ Bl,
                     const float* __restrict__ bias, float* __restrict__ Cf,
                     __nv_bfloat16* __restrict__ Ch, __nv_bfloat16* __restrict__ Cl,
                     int mode, float scale)
{
    extern __shared__ __align__(16) char smem[];
    const uint32_t sb = smem_u32(smem);
    const int tid = threadIdx.x;
    const int lane = tid & 31, wid = tid >> 5;
    const int wm = wid & 3, wn = wid >> 2;
    const int m0 = blockIdx.y * 128, n0 = blockIdx.x * 128;

    float acc[2][8][4];
    #pragma unroll
    for (int mt = 0; mt < 2; mt++)
        #pragma unroll
        for (int nt = 0; nt < 8; nt++)
            #pragma unroll
            for (int c = 0; c < 4; c++) acc[mt][nt][c] = 0.f;

    const int lr = tid >> 3;
    const int lc = (tid & 7) * 8;

    auto issue = [&](int kci) {
        uint32_t base = sb + (uint32_t)(kci & 1) * STG;
        int kc = kci * KC;
        #pragma unroll
        for (int u = 0; u < 4; ++u) {
            int r = lr + u * 32;
            size_t ga = (size_t)(m0 + r) * DIM + kc + lc;
            size_t gb = (size_t)(n0 + r) * DIM + kc + lc;
            uint32_t so = (uint32_t)(r * LDT + lc) * 2;
            cp16(base + OFF_AH + so, Ah + ga);
            cp16(base + OFF_AL + so, Al + ga);
            cp16(base + OFF_BH + so, Bh + gb);
            cp16(base + OFF_BL + so, Bl + gb);
        }
        cp_commit();
    };

    const uint32_t a_row = (uint32_t)(wm * 32 + (lane & 15));
    const uint32_t a_col = (uint32_t)((lane >> 4) << 3);
    const uint32_t b4_row = (uint32_t)((lane & 7) + ((lane >> 4) << 3));
    const uint32_t b4_col = (uint32_t)(((lane >> 3) & 1) << 3);

    issue(0);
    issue(1);

    for (int kci = 0; kci < NCH; ++kci) {
        if (kci + 2 >= NCH) cp_wait<0>(); else cp_wait<1>();
        __syncthreads();
        uint32_t base = sb + (uint32_t)(kci & 1) * STG;

        #pragma unroll
        for (int kk = 0; kk < KC; kk += 16) {
            uint32_t ahf[2][4], alf[2][4];
            #pragma unroll
            for (int mt = 0; mt < 2; mt++) {
                uint32_t off = ((a_row + mt * 16) * LDT + kk + a_col) * 2;
                ldm4(ahf[mt], base + OFF_AH + off);
                ldm4(alf[mt], base + OFF_AL + off);
            }
            #pragma unroll
            for (int ntp = 0; ntp < 4; ntp++) {
                uint32_t boff = ((wn * 64 + ntp * 16 + b4_row) * LDT + kk + b4_col) * 2;
                uint32_t bh4[4], bl4[4];
                ldm4(bh4, base + OFF_BH + boff);
                ldm4(bl4, base + OFF_BL + boff);
                #pragma unroll
                for (int mt = 0; mt < 2; mt++) {
                    mma_bf16(acc[mt][2*ntp],   ahf[mt], bh4);
                    mma_bf16(acc[mt][2*ntp],   ahf[mt], bl4);
                    mma_bf16(acc[mt][2*ntp],   alf[mt], bh4);
                    mma_bf16(acc[mt][2*ntp+1], ahf[mt], bh4 + 2);
                    mma_bf16(acc[mt][2*ntp+1], ahf[mt], bl4 + 2);
                    mma_bf16(acc[mt][2*ntp+1], alf[mt], bh4 + 2);
                }
            }
        }
        __syncthreads();
        if (kci + 2 < NCH) issue(kci + 2);
    }

    // ---- epilogue ----
    const int row = lane >> 2;
    const int col2 = (lane & 3) * 2;
    #pragma unroll
    for (int nt = 0; nt < 8; nt++) {
        int n = n0 + wn * 64 + nt * 8 + col2;
        float bx = bias[n], by = bias[n + 1];
        #pragma unroll
        for (int mt = 0; mt < 2; mt++) {
            int m = m0 + wm * 32 + mt * 16 + row;
            if (mode == 0) {
                *(float2*)(Cf + (size_t)m * DIM + n) =
                    make_float2(acc[mt][nt][0] + bx, acc[mt][nt][1] + by);
                *(float2*)(Cf + (size_t)(m + 8) * DIM + n) =
                    make_float2(acc[mt][nt][2] + bx, acc[mt][nt][3] + by);
            } else {
                int h = n >> 6, d0 = n & 63;
                int b_ = m >> 11, s_ = m & 2047;
                size_t base = ((size_t)(b_ * NH + h) * SEQ + s_) * DKH + d0;
                uint32_t H, L;
                split2((acc[mt][nt][0] + bx) * scale, (acc[mt][nt][1] + by) * scale, H, L);
                *(uint32_t*)(Ch + base) = H;
                *(uint32_t*)(Cl + base) = L;
                split2((acc[mt][nt][2] + bx) * scale, (acc[mt][nt][3] + by) * scale, H, L);
                *(uint32_t*)(Ch + base + 8 * DKH) = H;
                *(uint32_t*)(Cl + base + 8 * DKH) = L;
            }
        }
    }
}

// ============================================================
// Tensor-core flash attention, presplit bf16 K/V via cp.async
// CTA: 128 q-rows of one (b,h). 8 warps, 16 q-rows each.
// Writes output split (hi/lo) straight into g_ah/g_al [B,S,D].
// ============================================================
#define ALD 72
#define ATILE 9216      // 64*72*2
#define ASTG  36864     // 4 tiles (Kh,Kl,Vh,Vl)
#define AT_SMEM 73728   // 2 stages
#define NKT (SEQ/64)    // 32

__global__ __launch_bounds__(256, 1)
void attn_mma_kernel(const int* __restrict__ mask)
{
    extern __shared__ __align__(16) char sm[];
    const uint32_t sb = smem_u32(sm);
    const int tid = threadIdx.x, lane = tid & 31, wid = tid >> 5;
    const int q0 = blockIdx.x * 128;
    const int h = blockIdx.y, b = blockIdx.z;

    const size_t hoff = ((size_t)b * NH + h) * SEQ;

    // ---- stage Q hi/lo (already scaled by 0.125 in projection) ----
    {
        const __nv_bfloat16* Qh = g_Qh + (hoff + q0) * DKH;
        const __nv_bfloat16* Ql = g_Ql + (hoff + q0) * DKH;
        #pragma unroll
        for (int u = 0; u < 4; ++u) {
            int idx = tid + u * 256;          // 0..1023
            int r = idx >> 3, c8 = (idx & 7) << 3;
            uint32_t so = (uint32_t)(r * ALD + c8) * 2;
            size_t go = (size_t)r * DKH + c8;
            cp16(sb + so, Qh + go);
            cp16(sb + 18432 + so, Ql + go);
        }
        cp_commit();
        cp_wait<0>();
        __syncthreads();
    }

    uint32_t qh[4][4], ql[4][4];
    {
        uint32_t a_row = (uint32_t)(wid * 16 + (lane & 15));
        uint32_t a_col = (uint32_t)((lane >> 4) << 3);
        #pragma unroll
        for (int kk = 0; kk < 4; ++kk) {
            uint32_t off = (a_row * ALD + kk * 16 + a_col) * 2;
            ldm4(qh[kk], sb + off);
            ldm4(ql[kk], sb + 18432 + off);
        }
    }
    __syncthreads();    // Q smem area now reusable as pipeline stage 0

    float oacc[8][4];
    #pragma unroll
    for (int nt = 0; nt < 8; nt++)
        #pragma unroll
        for (int c = 0; c < 4; c++) oacc[nt][c] = 0.f;
    float mi0 = -1e30f, mi1 = -1e30f, li0 = 0.f, li1 = 0.f;

    const int row0 = wid * 16 + (lane >> 2);
    const int col2 = (lane & 3) * 2;
    const int* mrow0 = mask + ((size_t)b * SEQ + q0 + row0) * SEQ + col2;
    const int* mrow1 = mrow0 + 8 * SEQ;

    const uint32_t kb4_row = (uint32_t)((lane & 7) + ((lane >> 4) << 3));
    const uint32_t kb4_col = (uint32_t)(((lane >> 3) & 1) << 3);
    const uint32_t v4_row = (uint32_t)(lane & 15);
    const uint32_t v4_col = (uint32_t)((lane >> 4) << 3);

    auto issue = [&](int t) {
        uint32_t base = sb + (uint32_t)(t & 1) * ASTG;
        size_t koff = (hoff + t * 64) * DKH;
        #pragma unroll
        for (int u = 0; u < 2; ++u) {
            int idx = tid + u * 256;          // 0..511
            int r = idx >> 3, c8 = (idx & 7) << 3;
            uint32_t so = (uint32_t)(r * ALD + c8) * 2;
            size_t go = koff + (size_t)r * DKH + c8;
            cp16(base + 0     + so, g_Kh + go);
            cp16(base + 9216  + so, g_Kl + go);
            cp16(base + 18432 + so, g_Vh + go);
            cp16(base + 27648 + so, g_Vl + go);
        }
        cp_commit();
    };

    issue(0);
    issue(1);

    for (int t = 0; t < NKT; ++t) {
        if (t + 2 >= NKT) cp_wait<0>(); else cp_wait<1>();
        __syncthreads();
        uint32_t base = sb + (uint32_t)(t & 1) * ASTG;
        int k0 = t * 64;

        // ---- S = Q K^T (bf16x3), K via ldm4 pairs ----
        float sacc[8][4];
        #pragma unroll
        for (int nt = 0; nt < 8; nt++)
            #pragma unroll
            for (int c = 0; c < 4; c++) sacc[nt][c] = 0.f;
        #pragma unroll
        for (int kk = 0; kk < 4; ++kk) {
            #pragma unroll
            for (int ntp = 0; ntp < 4; ++ntp) {
                uint32_t off = ((ntp * 16 + kb4_row) * ALD + kk * 16 + kb4_col) * 2;
                uint32_t kh4[4], kl4[4];
                ldm4(kh4, base + off);
                ldm4(kl4, base + 9216 + off);
                mma_bf16(sacc[2*ntp],   qh[kk], kh4);
                mma_bf16(sacc[2*ntp],   qh[kk], kl4);
                mma_bf16(sacc[2*ntp],   ql[kk], kh4);
                mma_bf16(sacc[2*ntp+1], qh[kk], kh4 + 2);
                mma_bf16(sacc[2*ntp+1], qh[kk], kl4 + 2);
                mma_bf16(sacc[2*ntp+1], ql[kk], kh4 + 2);
            }
        }

        // ---- mask + online softmax ----
        float mx0 = -1e30f, mx1 = -1e30f;
        #pragma unroll
        for (int nt = 0; nt < 8; nt++) {
            int2 m0 = *(const int2*)(mrow0 + k0 + nt * 8);
            int2 m1 = *(const int2*)(mrow1 + k0 + nt * 8);
            sacc[nt][0] = m0.x ? sacc[nt][0] : -1e9f;
            sacc[nt][1] = m0.y ? sacc[nt][1] : -1e9f;
            sacc[nt][2] = m1.x ? sacc[nt][2] : -1e9f;
            sacc[nt][3] = m1.y ? sacc[nt][3] : -1e9f;
            mx0 = fmaxf(mx0, fmaxf(sacc[nt][0], sacc[nt][1]));
            mx1 = fmaxf(mx1, fmaxf(sacc[nt][2], sacc[nt][3]));
        }
        #pragma unroll
        for (int o = 1; o <= 2; o <<= 1) {
            mx0 = fmaxf(mx0, __shfl_xor_sync(0xffffffffu, mx0, o));
            mx1 = fmaxf(mx1, __shfl_xor_sync(0xffffffffu, mx1, o));
        }
        float mn0 = fmaxf(mi0, mx0), mn1 = fmaxf(mi1, mx1);
        float corr0 = __expf(mi0 - mn0), corr1 = __expf(mi1 - mn1);
        mi0 = mn0; mi1 = mn1;

        float rs0 = 0.f, rs1 = 0.f;
        #pragma unroll
        for (int nt = 0; nt < 8; nt++) {
            sacc[nt][0] = __expf(sacc[nt][0] - mn0);
            sacc[nt][1] = __expf(sacc[nt][1] - mn0);
            sacc[nt][2] = __expf(sacc[nt][2] - mn1);
            sacc[nt][3] = __expf(sacc[nt][3] - mn1);
            rs0 += sacc[nt][0] + sacc[nt][1];
            rs1 += sacc[nt][2] + sacc[nt][3];
        }
        #pragma unroll
        for (int o = 1; o <= 2; o <<= 1) {
            rs0 += __shfl_xor_sync(0xffffffffu, rs0, o);
            rs1 += __shfl_xor_sync(0xffffffffu, rs1, o);
        }
        li0 = li0 * corr0 + rs0;
        li1 = li1 * corr1 + rs1;
        #pragma unroll
        for (int nt = 0; nt < 8; nt++) {
            oacc[nt][0] *= corr0; oacc[nt][1] *= corr0;
            oacc[nt][2] *= corr1; oacc[nt][3] *= corr1;
        }

        // ---- P fragments (bf16 hi/lo) straight from S accumulators ----
        uint32_t ph[4][4], pl[4][4];
        #pragma unroll
        for (int kt = 0; kt < 4; ++kt) {
            split2(sacc[2*kt][0],   sacc[2*kt][1],   ph[kt][0], pl[kt][0]);
            split2(sacc[2*kt][2],   sacc[2*kt][3],   ph[kt][1], pl[kt][1]);
            split2(sacc[2*kt+1][0], sacc[2*kt+1][1], ph[kt][2], pl[kt][2]);
            split2(sacc[2*kt+1][2], sacc[2*kt+1][3], ph[kt][3], pl[kt][3]);
        }

        // ---- O += P V (bf16x3), V via ldm4.trans pairs ----
        #pragma unroll
        for (int kt = 0; kt < 4; ++kt) {
            #pragma unroll
            for (int ndp = 0; ndp < 4; ++ndp) {
                uint32_t off = ((kt * 16 + v4_row) * ALD + ndp * 16 + v4_col) * 2;
                uint32_t vh4[4], vl4[4];
                ldm4t(vh4, base + 18432 + off);
                ldm4t(vl4, base + 27648 + off);
                mma_bf16(oacc[2*ndp],   ph[kt], vh4);
                mma_bf16(oacc[2*ndp],   ph[kt], vl4);
                mma_bf16(oacc[2*ndp],   pl[kt], vh4);
                mma_bf16(oacc[2*ndp+1], ph[kt], vh4 + 2);
                mma_bf16(oacc[2*ndp+1], ph[kt], vl4 + 2);
                mma_bf16(oacc[2*ndp+1], pl[kt], vh4 + 2);
            }
        }
        __syncthreads();
        if (t + 2 < NKT) issue(t + 2);
    }

    // ---- normalize + split-store into g_ah/g_al [B,S,D] ----
    float inv0 = 1.f / li0, inv1 = 1.f / li1;
    size_t o0 = ((size_t)b * SEQ + q0 + row0) * DIM + h * DKH + col2;
    #pragma unroll
    for (int nd = 0; nd < 8; nd++) {
        uint32_t H, L;
        split2(oacc[nd][0] * inv0, oacc[nd][1] * inv0, H, L);
        *(uint32_t*)(g_ah + o0 + nd * 8) = H;
        *(uint32_t*)(g_al + o0 + nd * 8) = L;
        split2(oacc[nd][2] * inv1, oacc[nd][3] * inv1, H, L);
        *(uint32_t*)(g_ah + o0 + 8 * DIM + nd * 8) = H;
        *(uint32_t*)(g_al + o0 + 8 * DIM + nd * 8) = L;
    }
}

// ============================================================
extern "C" void kernel_launch(void* const* d_in, const int* in_sizes, int n_in,
                              void* d_out, int out_size)
{
    const float* q    = (const float*)d_in[0];
    const float* k    = (const float*)d_in[1];
    const float* v    = (const float*)d_in[2];
    const int*   mask = (const int*)  d_in[3];
    const float* Wq   = (const float*)d_in[4];
    const float* bq   = (const float*)d_in[5];
    const float* Wk   = (const float*)d_in[6];
    const float* bk   = (const float*)d_in[7];
    const float* Wv   = (const float*)d_in[8];
    const float* bv   = (const float*)d_in[9];
    const float* Wo   = (const float*)d_in[10];
    const float* bo   = (const float*)d_in[11];
    float* out = (float*)d_out;

    __nv_bfloat16 *pah, *pal, *pwh, *pwl, *pQh, *pQl, *pKh, *pKl, *pVh, *pVl;
    cudaGetSymbolAddress((void**)&pah, g_ah);
    cudaGetSymbolAddress((void**)&pal, g_al);
    cudaGetSymbolAddress((void**)&pwh, g_wh);
    cudaGetSymbolAddress((void**)&pwl, g_wl);
    cudaGetSymbolAddress((void**)&pQh, g_Qh);
    cudaGetSymbolAddress((void**)&pQl, g_Ql);
    cudaGetSymbolAddress((void**)&pKh, g_Kh);
    cudaGetSymbolAddress((void**)&pKl, g_Kl);
    cudaGetSymbolAddress((void**)&pVh, g_Vh);
    cudaGetSymbolAddress((void**)&pVl, g_Vl);

    cudaFuncSetAttribute(mma_gemm_kernel, cudaFuncAttributeMaxDynamicSharedMemorySize, MM_SMEM);
    cudaFuncSetAttribute(attn_mma_kernel, cudaFuncAttributeMaxDynamicSharedMemorySize, AT_SMEM);

    const int n4_act = MTOT * DIM / 4;
    const int n4_w   = DIM * DIM / 4;
    dim3 gg(DIM / 128, MTOT / 128);   // (8, 64)

    // Q projection -> bf16 hi/lo, pre-scaled by 1/sqrt(DK)=0.125
    split_kernel<<<n4_act / 256, 256>>>((const float4*)q, (uint2*)pah, (uint2*)pal, n4_act);
    split_kernel<<<n4_w / 256, 256>>>((const float4*)Wq, (uint2*)pwh, (uint2*)pwl, n4_w);
    mma_gemm_kernel<<<gg, 256, MM_SMEM>>>(pah, pal, pwh, pwl, bq, nullptr, pQh, pQl, 1, 0.125f);
    // K projection
    split_kernel<<<n4_act / 256, 256>>>((const float4*)k, (uint2*)pah, (uint2*)pal, n4_act);
    split_kernel<<<n4_w / 256, 256>>>((const float4*)Wk, (uint2*)pwh, (uint2*)pwl, n4_w);
    mma_gemm_kernel<<<gg, 256, MM_SMEM>>>(pah, pal, pwh, pwl, bk, nullptr, pKh, pKl, 1, 1.0f);
    // V projection
    split_kernel<<<n4_act / 256, 256>>>((const float4*)v, (uint2*)pah, (uint2*)pal, n4_act);
    split_kernel<<<n4_w / 256, 256>>>((const float4*)Wv, (uint2*)pwh, (uint2*)pwl, n4_w);
    mma_gemm_kernel<<<gg, 256, MM_SMEM>>>(pah, pal, pwh, pwl, bv, nullptr, pVh, pVl, 1, 1.0f);

    // attention (writes split output into g_ah/g_al)
    attn_mma_kernel<<<dim3(SEQ / 128, NH, Bsz), 256, AT_SMEM>>>(mask);

    // output projection (fp32 out)
    split_kernel<<<n4_w / 256, 256>>>((const float4*)Wo, (uint2*)pwh, (uint2*)pwl, n4_w);
    mma_gemm_kernel<<<gg, 256, MM_SMEM>>>(pah, pal, pwh, pwl, bo, out, nullptr, nullptr, 0, 1.0f);
}